// round 10
// baseline (speedup 1.0000x reference)
#include <cuda_runtime.h>
#include <cuda_bf16.h>
#include <cstdint>
#include <math.h>

// ---------------- problem constants ----------------
#define B_Q     1024
#define DM      4096
#define NH      32
#define NKV     8
#define HD      128
#define PAST    4096
#define SINKS_N 4
#define SCALE_QK 0.08838834764831845f   // 1/sqrt(128)
#define QSCALE   0.12751878662109375f   // fl(SCALE_QK * log2(e))

// ---------------- scratch ----------------
__device__ float g_qbuf[B_Q * NH * HD];
__device__ float g_kbuf[B_Q * NKV * HD];
__device__ float g_vbuf[B_Q * NKV * HD];
__device__ float g_kt[NKV * B_Q * HD];
__device__ float g_vt[NKV * B_Q * HD];
__device__ float g_attn[B_Q * NH * HD];

// ---------------- helpers ----------------
__device__ __forceinline__ uint32_t smem_u32(const void* p) {
    uint32_t a;
    asm("{ .reg .u64 t; cvta.to.shared.u64 t, %1; cvt.u32.u64 %0, t; }" : "=r"(a) : "l"(p));
    return a;
}
__device__ __forceinline__ unsigned f2tf(float x) {
    unsigned u; asm("cvt.rna.tf32.f32 %0, %1;" : "=r"(u) : "f"(x)); return u;
}
__device__ __forceinline__ float f2tff(float x) { return __uint_as_float(f2tf(x)); }

__device__ __forceinline__ void mma_tf32(float d[4],
    unsigned a0, unsigned a1, unsigned a2, unsigned a3, unsigned b0, unsigned b1)
{
    asm volatile(
        "mma.sync.aligned.m16n8k8.row.col.f32.tf32.tf32.f32 "
        "{%0,%1,%2,%3},{%4,%5,%6,%7},{%8,%9},{%0,%1,%2,%3};"
        : "+f"(d[0]), "+f"(d[1]), "+f"(d[2]), "+f"(d[3])
        : "r"(a0), "r"(a1), "r"(a2), "r"(a3), "r"(b0), "r"(b1));
}
__device__ __forceinline__ void ldm_x4(unsigned a[4], uint32_t addr) {
    asm volatile("ldmatrix.sync.aligned.m8n8.x4.shared.b16 {%0,%1,%2,%3}, [%4];"
        : "=r"(a[0]), "=r"(a[1]), "=r"(a[2]), "=r"(a[3]) : "r"(addr));
}

// ---------------- GEMM core (verified R5/R7 version, frozen) ----------------
__device__ __forceinline__ void gemm_core(
    const float* __restrict__ A, const float* __restrict__ B,
    float* __restrict__ C, int N, int K, int m0, int n0, float* smg)
{
    float* As[2] = { smg, smg + 128 * 36 };
    float* Bs[2] = { smg + 2 * 128 * 36, smg + 2 * 128 * 36 + 32 * 132 };

    const int tid  = threadIdx.x;
    const int w    = tid >> 5, lane = tid & 31;
    const int g    = lane >> 2, cq = lane & 3;
    const int wm   = w & 1, wn = w >> 1;

    const int ar  = tid >> 3, ac4 = (tid & 7) * 4;
    const int bkr = tid >> 5, bn4 = (tid & 31) * 4;

    const int lrow = ((lane >> 3) & 1) * 8 + (lane & 7);
    const int lcol = (lane >> 4) * 4;
    int aoff[4];
#pragma unroll
    for (int mt = 0; mt < 4; mt++)
        aoff[mt] = ((wm * 64 + mt * 16 + lrow) * 36 + lcol) * 4;
    const uint32_t as_u[2] = { smem_u32(As[0]), smem_u32(As[1]) };

    float acc[4][4][4];
#pragma unroll
    for (int i = 0; i < 4; i++)
#pragma unroll
        for (int j = 0; j < 4; j++)
#pragma unroll
            for (int r = 0; r < 4; r++) acc[i][j][r] = 0.f;

    const int ns = K >> 5;
    float4 ra[4], rb[4];
#pragma unroll
    for (int p = 0; p < 4; p++) {
        ra[p] = *(const float4*)&A[(size_t)(m0 + ar + p * 32) * K + ac4];
        rb[p] = *(const float4*)&B[(size_t)(bkr + p * 8) * N + n0 + bn4];
    }

    for (int i = 0; i < ns; i++) {
        float* Ab = As[i & 1];
        float* Bb = Bs[i & 1];
        const uint32_t abu = as_u[i & 1];
#pragma unroll
        for (int p = 0; p < 4; p++) {
            *(float4*)&Ab[(ar + p * 32) * 36 + ac4] =
                make_float4(f2tff(ra[p].x), f2tff(ra[p].y), f2tff(ra[p].z), f2tff(ra[p].w));
            *(float4*)&Bb[(bkr + p * 8) * 132 + bn4] =
                make_float4(f2tff(rb[p].x), f2tff(rb[p].y), f2tff(rb[p].z), f2tff(rb[p].w));
        }
        __syncthreads();

        if (i + 1 < ns) {
            const int k0 = (i + 1) * 32;
#pragma unroll
            for (int p = 0; p < 4; p++) {
                ra[p] = *(const float4*)&A[(size_t)(m0 + ar + p * 32) * K + k0 + ac4];
                rb[p] = *(const float4*)&B[(size_t)(k0 + bkr + p * 8) * N + n0 + bn4];
            }
        }

#pragma unroll
        for (int ks = 0; ks < 4; ks++) {
            const int k = ks * 8 + cq;
            unsigned a[4][4], b[4][2];
#pragma unroll
            for (int mt = 0; mt < 4; mt++)
                ldm_x4(a[mt], abu + aoff[mt] + ks * 32);
#pragma unroll
            for (int nt = 0; nt < 4; nt++) {
                int n = wn * 32 + nt * 8 + g;
                b[nt][0] = __float_as_uint(Bb[k * 132 + n]);
                b[nt][1] = __float_as_uint(Bb[(k + 4) * 132 + n]);
            }
#pragma unroll
            for (int mt = 0; mt < 4; mt++)
#pragma unroll
                for (int nt = 0; nt < 4; nt++)
                    mma_tf32(acc[mt][nt], a[mt][0], a[mt][1], a[mt][2], a[mt][3],
                             b[nt][0], b[nt][1]);
        }
    }

#pragma unroll
    for (int mt = 0; mt < 4; mt++)
#pragma unroll
        for (int nt = 0; nt < 4; nt++) {
            int r  = m0 + wm * 64 + mt * 16 + g;
            int cc = n0 + wn * 32 + nt * 8 + 2 * cq;
            *(float2*)&C[(size_t)r * N + cc]       = make_float2(acc[mt][nt][0], acc[mt][nt][1]);
            *(float2*)&C[(size_t)(r + 8) * N + cc] = make_float2(acc[mt][nt][2], acc[mt][nt][3]);
        }
}

__global__ __launch_bounds__(256, 2) void qkv_gemm(
    const float* __restrict__ hidden, const float* __restrict__ Wq,
    const float* __restrict__ Wk, const float* __restrict__ Wv)
{
    extern __shared__ float smg[];
    const int bx = blockIdx.x;
    const float* B; float* C; int N, n0;
    if (bx < 32)      { B = Wq; C = g_qbuf; N = NH * HD;  n0 = bx * 128; }
    else if (bx < 40) { B = Wk; C = g_kbuf; N = NKV * HD; n0 = (bx - 32) * 128; }
    else              { B = Wv; C = g_vbuf; N = NKV * HD; n0 = (bx - 40) * 128; }
    gemm_core(hidden, B, C, N, DM, blockIdx.y * 128, n0, smg);
}

__global__ __launch_bounds__(256, 2) void out_gemm(
    const float* __restrict__ A, const float* __restrict__ Wo, float* __restrict__ C)
{
    extern __shared__ float smg[];
    gemm_core(A, Wo, C, DM, NH * HD, blockIdx.y * 128, blockIdx.x * 128, smg);
}

// ---------------- RoPE + transpose (K/V only; Q fused into attention) ----------------
__global__ void rope_kernel(const float* __restrict__ cosT, const float* __restrict__ sinT)
{
    const int qi   = blockIdx.x;
    const int slot = blockIdx.y;
    const int d    = threadIdx.x;
    const int pos  = PAST + qi;

    if (slot < NKV) {
        const int h = slot;
        const float c = cosT[pos * HD + d];
        const float s = sinT[pos * HD + d];
        const float* src = g_kbuf + (size_t)qi * (NKV * HD) + h * HD;
        float x = src[d], y = src[d ^ 64];
        g_kt[((size_t)h * B_Q + qi) * HD + d] = x * c + ((d < 64) ? -y : y) * s;
    } else {
        const int h = slot - NKV;
        g_vt[((size_t)h * B_Q + qi) * HD + d] =
            g_vbuf[(size_t)qi * (NKV * HD) + h * HD + d];
    }
}

// ---------------- Flash attention, tf32 mma, pipelined + full ldmatrix ----------------
// 256 threads = 8 warps. Q-tile 128 (warp w owns rows w*16..+15), K-tile 64.
// Q: RoPE + scale*log2e folded at staging, register A-frags. exp2-domain softmax
// with rescale-skip (corr==1 fast path) and unmasked-tile fast path.
__global__ __launch_bounds__(256) void attn_tc(
    const float* __restrict__ pk, const float* __restrict__ pv,
    const float* __restrict__ cosT, const float* __restrict__ sinT)
{
    extern __shared__ float sm[];
    float* KsBuf[2] = { sm,                sm + 64 * 132 };
    float* VtBuf[2] = { sm + 2 * 64 * 132, sm + 2 * 64 * 132 + 128 * 68 };
    float (*Ps)[68] = (float(*)[68])(sm + 2 * 64 * 132 + 2 * 128 * 68);  // 128 x 68

    const int tid = threadIdx.x;
    const int w = tid >> 5, lane = tid & 31;
    const int g = lane >> 2, cq = lane & 3;
    const int q0 = blockIdx.x * 128;
    const int h  = blockIdx.y;
    const int kvh = h >> 2;
    const int rbase = w * 16;

    // ---- stage Q with fused RoPE + scale fold (stride 132), ldmatrix -> regs ----
#pragma unroll
    for (int p = 0; p < 16; p++) {
        int e = p * 256 + tid;
        int row = e >> 5, d4 = (e & 31) * 4;
        const float* src = &g_qbuf[(size_t)(q0 + row) * (NH * HD) + h * HD];
        float4 x = *(const float4*)&src[d4];
        float4 y = *(const float4*)&src[d4 ^ 64];
        const int pos = PAST + q0 + row;
        float4 c = *(const float4*)&cosT[pos * HD + d4];
        float4 s = *(const float4*)&sinT[pos * HD + d4];
        float sgn = (d4 < 64) ? -1.f : 1.f;
        float4 r;
        r.x = (x.x * c.x + sgn * y.x * s.x) * QSCALE;
        r.y = (x.y * c.y + sgn * y.y * s.y) * QSCALE;
        r.z = (x.z * c.z + sgn * y.z * s.z) * QSCALE;
        r.w = (x.w * c.w + sgn * y.w * s.w) * QSCALE;
        *(float4*)&sm[row * 132 + d4] =
            make_float4(f2tff(r.x), f2tff(r.y), f2tff(r.z), f2tff(r.w));
    }
    __syncthreads();

    const int lrow = rbase + ((lane >> 3) & 1) * 8 + (lane & 7);
    const int lcol = (lane >> 4) * 4;
    const uint32_t qmat = smem_u32(sm) + (lrow * 132 + lcol) * 4;
    unsigned qf[16][4];
#pragma unroll
    for (int ks = 0; ks < 16; ks++)
        ldm_x4(qf[ks], qmat + ks * 32);
    __syncthreads();   // Q staging reads done before K0/V0 STS

    const uint32_t pmat = smem_u32(&Ps[0][0]) + (lrow * 68 + lcol) * 4;

    const int g3 = lane >> 3, l7 = lane & 7;
    uint32_t kmat[2][4], vmat[2][8];
#pragma unroll
    for (int b = 0; b < 2; b++) {
        const uint32_t kb = smem_u32(KsBuf[b]);
        const uint32_t vb = smem_u32(VtBuf[b]);
#pragma unroll
        for (int ntp = 0; ntp < 4; ntp++) {
            int row = ntp * 16 + (g3 >> 1) * 8 + l7;
            kmat[b][ntp] = kb + (row * 132 + (g3 & 1) * 4) * 4;
        }
#pragma unroll
        for (int ntp = 0; ntp < 8; ntp++) {
            int row = ntp * 16 + (g3 >> 1) * 8 + l7;
            vmat[b][ntp] = vb + (row * 68 + (g3 & 1) * 4) * 4;
        }
    }

    float m_i[2], l_i[2];
    float o[16][4];
    m_i[0] = m_i[1] = -1e30f;
    l_i[0] = l_i[1] = 0.f;
#pragma unroll
    for (int nt = 0; nt < 16; nt++)
#pragma unroll
        for (int r = 0; r < 4; r++) o[nt][r] = 0.f;

    const int ntiles = ((3072 + q0 + 127) >> 6) + 1;
    const int limw   = 3072 + q0 + rbase;   // warp-min causal limit (row g=0, half 0)
    const int d4c = (lane * 4) & 127;
    const int vd  = tid & 127;
    const int vk0 = (tid >> 7) * 32;

    float4 rk[8];
    float  rv[32];
#define LOAD_K(KT) do { \
        const int _jb = (KT) * 64; \
        _Pragma("unroll") \
        for (int p = 0; p < 8; p++) { \
            int j = _jb + p * 8 + w; \
            int kp = (j < SINKS_N) ? j : j + 1024; \
            rk[p] = (kp < PAST) \
                ? *(const float4*)&pk[((size_t)kvh * PAST + kp) * HD + d4c] \
                : *(const float4*)&g_kt[((size_t)kvh * B_Q + (kp - PAST)) * HD + d4c]; \
        } \
    } while (0)
#define LOAD_V(KT) do { \
        const int _jb = (KT) * 64 + vk0; \
        _Pragma("unroll") \
        for (int j = 0; j < 32; j++) { \
            int jj = _jb + j; \
            int kp = (jj < SINKS_N) ? jj : jj + 1024; \
            rv[j] = (kp < PAST) \
                ? pv[((size_t)kvh * PAST + kp) * HD + vd] \
                : g_vt[((size_t)kvh * B_Q + (kp - PAST)) * HD + vd]; \
        } \
    } while (0)
#define STS_K(BUF) do { \
        float* _d = KsBuf[BUF]; \
        _Pragma("unroll") \
        for (int p = 0; p < 8; p++) \
            *(float4*)&_d[(p * 8 + w) * 132 + d4c] = \
                make_float4(f2tff(rk[p].x), f2tff(rk[p].y), f2tff(rk[p].z), f2tff(rk[p].w)); \
    } while (0)
#define STS_V(BUF) do { \
        float* _d = VtBuf[BUF]; \
        _Pragma("unroll") \
        for (int p = 0; p < 8; p++) \
            *(float4*)&_d[vd * 68 + vk0 + p * 4] = \
                make_float4(f2tff(rv[p * 4]), f2tff(rv[p * 4 + 1]), \
                            f2tff(rv[p * 4 + 2]), f2tff(rv[p * 4 + 3])); \
    } while (0)

    // prologue: tile 0 into buffer 0
    LOAD_K(0); LOAD_V(0);
    STS_K(0);  STS_V(0);

    for (int kt = 0; kt < ntiles; kt++) {
        const int jbase = kt * 64;
        const int buf = kt & 1;
        const bool pf = (kt + 1 < ntiles);
        __syncthreads();   // buffer `buf` ready; prior readers of buf^1 done

        if (pf) LOAD_K(kt + 1);   // LDG issues early; consumed after softmax

        // ---- S = Q @ K^T : 16 rows x 64 keys per warp (exp2-scaled domain) ----
        float s[8][4];
#pragma unroll
        for (int nt = 0; nt < 8; nt++)
#pragma unroll
            for (int r = 0; r < 4; r++) s[nt][r] = 0.f;

#pragma unroll
        for (int ks = 0; ks < 16; ks++) {
#pragma unroll
            for (int ntp = 0; ntp < 4; ntp++) {
                unsigned bf[4];
                ldm_x4(bf, kmat[buf][ntp] + ks * 32);
                mma_tf32(s[2 * ntp],     qf[ks][0], qf[ks][1], qf[ks][2], qf[ks][3], bf[0], bf[1]);
                mma_tf32(s[2 * ntp + 1], qf[ks][0], qf[ks][1], qf[ks][2], qf[ks][3], bf[2], bf[3]);
            }
        }

        // ---- online softmax (base-2 domain), fast paths ----
#pragma unroll
        for (int half = 0; half < 2; half++) {
            const int rl  = rbase + g + half * 8;
            float mx = -1e30f;
            if (jbase + 63 <= limw + half * 8) {
                // fully unmasked for every row of this half (warp-uniform)
#pragma unroll
                for (int nt = 0; nt < 8; nt++) {
                    mx = fmaxf(mx, fmaxf(s[nt][half * 2], s[nt][half * 2 + 1]));
                }
            } else {
                const int lim = 3072 + q0 + rl;
#pragma unroll
                for (int nt = 0; nt < 8; nt++)
#pragma unroll
                    for (int rr = 0; rr < 2; rr++) {
                        int jg = jbase + nt * 8 + 2 * cq + rr;
                        float v = (jg <= lim) ? s[nt][half * 2 + rr] : -1e30f;
                        s[nt][half * 2 + rr] = v;
                        mx = fmaxf(mx, v);
                    }
            }
            mx = fmaxf(mx, __shfl_xor_sync(0xffffffffu, mx, 1));
            mx = fmaxf(mx, __shfl_xor_sync(0xffffffffu, mx, 2));
            if (mx > m_i[half]) {
                // max changed: rescale running state (rare after warm-up)
                float corr = exp2f(m_i[half] - mx);
                m_i[half] = mx;
                l_i[half] *= corr;
#pragma unroll
                for (int nt = 0; nt < 16; nt++) {
                    o[nt][half * 2]     *= corr;
                    o[nt][half * 2 + 1] *= corr;
                }
            }
            const float mnew = m_i[half];
            float rs = 0.f;
#pragma unroll
            for (int nt = 0; nt < 8; nt++) {
                float p0 = exp2f(s[nt][half * 2]     - mnew);
                float p1 = exp2f(s[nt][half * 2 + 1] - mnew);
                rs += p0 + p1;
                *(float2*)&Ps[rl][nt * 8 + 2 * cq] = make_float2(f2tff(p0), f2tff(p1));
            }
            rs += __shfl_xor_sync(0xffffffffu, rs, 1);
            rs += __shfl_xor_sync(0xffffffffu, rs, 2);
            l_i[half] += rs;
        }
        __syncwarp();   // Ps is warp-private

        if (pf) { STS_K(buf ^ 1); LOAD_V(kt + 1); }

        // ---- O += P @ V : 16 rows x 128 d per warp, k-dim 64 ----
#pragma unroll
        for (int ks = 0; ks < 8; ks++) {
            unsigned a[4];
            ldm_x4(a, pmat + ks * 32);
#pragma unroll
            for (int ntp = 0; ntp < 8; ntp++) {
                unsigned bf[4];
                ldm_x4(bf, vmat[buf][ntp] + ks * 32);
                mma_tf32(o[2 * ntp],     a[0], a[1], a[2], a[3], bf[0], bf[1]);
                mma_tf32(o[2 * ntp + 1], a[0], a[1], a[2], a[3], bf[2], bf[3]);
            }
        }

        if (pf) STS_V(buf ^ 1);
    }

    // ---- epilogue ----
    float inv0 = 1.0f / l_i[0];
    float inv1 = 1.0f / l_i[1];
    int row0 = q0 + rbase + g;
#pragma unroll
    for (int nt = 0; nt < 16; nt++) {
        int dd = nt * 8 + 2 * cq;
        *(float2*)&g_attn[(size_t)row0 * (NH * HD) + h * HD + dd] =
            make_float2(o[nt][0] * inv0, o[nt][1] * inv0);
        *(float2*)&g_attn[(size_t)(row0 + 8) * (NH * HD) + h * HD + dd] =
            make_float2(o[nt][2] * inv1, o[nt][3] * inv1);
    }
}

// ---------------- launch ----------------
extern "C" void kernel_launch(void* const* d_in, const int* in_sizes, int n_in,
                              void* d_out, int out_size)
{
    (void)in_sizes; (void)n_in; (void)out_size;
    const float* hidden = (const float*)d_in[0];
    const float* Wq     = (const float*)d_in[1];
    const float* Wk     = (const float*)d_in[2];
    const float* Wv     = (const float*)d_in[3];
    const float* Wo     = (const float*)d_in[4];
    const float* past_k = (const float*)d_in[5];
    const float* past_v = (const float*)d_in[6];
    const float* cosT   = (const float*)d_in[7];
    const float* sinT   = (const float*)d_in[8];

    void *p_attn;
    cudaGetSymbolAddress(&p_attn, g_attn);

    const int gemm_smem = (2 * 128 * 36 + 2 * 32 * 132) * 4;            // 70656 B
    cudaFuncSetAttribute(qkv_gemm, cudaFuncAttributeMaxDynamicSharedMemorySize, gemm_smem);
    cudaFuncSetAttribute(out_gemm, cudaFuncAttributeMaxDynamicSharedMemorySize, gemm_smem);
    const int attn_smem = (2 * 64 * 132 + 2 * 128 * 68 + 128 * 68) * 4; // 172032 B
    cudaFuncSetAttribute(attn_tc, cudaFuncAttributeMaxDynamicSharedMemorySize, attn_smem);

    dim3 blk(256);
    qkv_gemm<<<dim3(48, 8), blk, gemm_smem>>>(hidden, Wq, Wk, Wv);
    rope_kernel<<<dim3(B_Q, 2 * NKV), 128>>>(cosT, sinT);
    attn_tc<<<dim3(B_Q / 128, NH), blk, attn_smem>>>(past_k, past_v, cosT, sinT);
    out_gemm<<<dim3(32, 8), blk, gemm_smem>>>((const float*)p_attn, Wo, (float*)d_out);
}

// round 11
// speedup vs baseline: 1.0325x; 1.0325x over previous
#include <cuda_runtime.h>
#include <cuda_bf16.h>
#include <cstdint>
#include <math.h>

// ---------------- problem constants ----------------
#define B_Q     1024
#define DM      4096
#define NH      32
#define NKV     8
#define HD      128
#define PAST    4096
#define SINKS_N 4
#define SCALE_QK 0.08838834764831845f   // 1/sqrt(128)
#define QSCALE   0.12751878662109375f   // fl(SCALE_QK * log2(e))

// ---------------- scratch ----------------
__device__ float g_qbuf[B_Q * NH * HD];
__device__ float g_kbuf[B_Q * NKV * HD];
__device__ float g_vbuf[B_Q * NKV * HD];
__device__ float g_kt[NKV * B_Q * HD];
__device__ float g_vt[NKV * B_Q * HD];
__device__ float g_attn[B_Q * NH * HD];

// ---------------- helpers ----------------
__device__ __forceinline__ uint32_t smem_u32(const void* p) {
    uint32_t a;
    asm("{ .reg .u64 t; cvta.to.shared.u64 t, %1; cvt.u32.u64 %0, t; }" : "=r"(a) : "l"(p));
    return a;
}
__device__ __forceinline__ unsigned f2tf(float x) {
    unsigned u; asm("cvt.rna.tf32.f32 %0, %1;" : "=r"(u) : "f"(x)); return u;
}
__device__ __forceinline__ float f2tff(float x) { return __uint_as_float(f2tf(x)); }

__device__ __forceinline__ void mma_tf32(float d[4],
    unsigned a0, unsigned a1, unsigned a2, unsigned a3, unsigned b0, unsigned b1)
{
    asm volatile(
        "mma.sync.aligned.m16n8k8.row.col.f32.tf32.tf32.f32 "
        "{%0,%1,%2,%3},{%4,%5,%6,%7},{%8,%9},{%0,%1,%2,%3};"
        : "+f"(d[0]), "+f"(d[1]), "+f"(d[2]), "+f"(d[3])
        : "r"(a0), "r"(a1), "r"(a2), "r"(a3), "r"(b0), "r"(b1));
}
__device__ __forceinline__ void ldm_x4(unsigned a[4], uint32_t addr) {
    asm volatile("ldmatrix.sync.aligned.m8n8.x4.shared.b16 {%0,%1,%2,%3}, [%4];"
        : "=r"(a[0]), "=r"(a[1]), "=r"(a[2]), "=r"(a[3]) : "r"(addr));
}

// ---------------- GEMM core (verified R5/R7 version, frozen) ----------------
__device__ __forceinline__ void gemm_core(
    const float* __restrict__ A, const float* __restrict__ B,
    float* __restrict__ C, int N, int K, int m0, int n0, float* smg)
{
    float* As[2] = { smg, smg + 128 * 36 };
    float* Bs[2] = { smg + 2 * 128 * 36, smg + 2 * 128 * 36 + 32 * 132 };

    const int tid  = threadIdx.x;
    const int w    = tid >> 5, lane = tid & 31;
    const int g    = lane >> 2, cq = lane & 3;
    const int wm   = w & 1, wn = w >> 1;

    const int ar  = tid >> 3, ac4 = (tid & 7) * 4;
    const int bkr = tid >> 5, bn4 = (tid & 31) * 4;

    const int lrow = ((lane >> 3) & 1) * 8 + (lane & 7);
    const int lcol = (lane >> 4) * 4;
    int aoff[4];
#pragma unroll
    for (int mt = 0; mt < 4; mt++)
        aoff[mt] = ((wm * 64 + mt * 16 + lrow) * 36 + lcol) * 4;
    const uint32_t as_u[2] = { smem_u32(As[0]), smem_u32(As[1]) };

    float acc[4][4][4];
#pragma unroll
    for (int i = 0; i < 4; i++)
#pragma unroll
        for (int j = 0; j < 4; j++)
#pragma unroll
            for (int r = 0; r < 4; r++) acc[i][j][r] = 0.f;

    const int ns = K >> 5;
    float4 ra[4], rb[4];
#pragma unroll
    for (int p = 0; p < 4; p++) {
        ra[p] = *(const float4*)&A[(size_t)(m0 + ar + p * 32) * K + ac4];
        rb[p] = *(const float4*)&B[(size_t)(bkr + p * 8) * N + n0 + bn4];
    }

    for (int i = 0; i < ns; i++) {
        float* Ab = As[i & 1];
        float* Bb = Bs[i & 1];
        const uint32_t abu = as_u[i & 1];
#pragma unroll
        for (int p = 0; p < 4; p++) {
            *(float4*)&Ab[(ar + p * 32) * 36 + ac4] =
                make_float4(f2tff(ra[p].x), f2tff(ra[p].y), f2tff(ra[p].z), f2tff(ra[p].w));
            *(float4*)&Bb[(bkr + p * 8) * 132 + bn4] =
                make_float4(f2tff(rb[p].x), f2tff(rb[p].y), f2tff(rb[p].z), f2tff(rb[p].w));
        }
        __syncthreads();

        if (i + 1 < ns) {
            const int k0 = (i + 1) * 32;
#pragma unroll
            for (int p = 0; p < 4; p++) {
                ra[p] = *(const float4*)&A[(size_t)(m0 + ar + p * 32) * K + k0 + ac4];
                rb[p] = *(const float4*)&B[(size_t)(k0 + bkr + p * 8) * N + n0 + bn4];
            }
        }

#pragma unroll
        for (int ks = 0; ks < 4; ks++) {
            const int k = ks * 8 + cq;
            unsigned a[4][4], b[4][2];
#pragma unroll
            for (int mt = 0; mt < 4; mt++)
                ldm_x4(a[mt], abu + aoff[mt] + ks * 32);
#pragma unroll
            for (int nt = 0; nt < 4; nt++) {
                int n = wn * 32 + nt * 8 + g;
                b[nt][0] = __float_as_uint(Bb[k * 132 + n]);
                b[nt][1] = __float_as_uint(Bb[(k + 4) * 132 + n]);
            }
#pragma unroll
            for (int mt = 0; mt < 4; mt++)
#pragma unroll
                for (int nt = 0; nt < 4; nt++)
                    mma_tf32(acc[mt][nt], a[mt][0], a[mt][1], a[mt][2], a[mt][3],
                             b[nt][0], b[nt][1]);
        }
    }

#pragma unroll
    for (int mt = 0; mt < 4; mt++)
#pragma unroll
        for (int nt = 0; nt < 4; nt++) {
            int r  = m0 + wm * 64 + mt * 16 + g;
            int cc = n0 + wn * 32 + nt * 8 + 2 * cq;
            *(float2*)&C[(size_t)r * N + cc]       = make_float2(acc[mt][nt][0], acc[mt][nt][1]);
            *(float2*)&C[(size_t)(r + 8) * N + cc] = make_float2(acc[mt][nt][2], acc[mt][nt][3]);
        }
}

__global__ __launch_bounds__(256, 2) void qkv_gemm(
    const float* __restrict__ hidden, const float* __restrict__ Wq,
    const float* __restrict__ Wk, const float* __restrict__ Wv)
{
    extern __shared__ float smg[];
    const int bx = blockIdx.x;
    const float* B; float* C; int N, n0;
    if (bx < 32)      { B = Wq; C = g_qbuf; N = NH * HD;  n0 = bx * 128; }
    else if (bx < 40) { B = Wk; C = g_kbuf; N = NKV * HD; n0 = (bx - 32) * 128; }
    else              { B = Wv; C = g_vbuf; N = NKV * HD; n0 = (bx - 40) * 128; }
    gemm_core(hidden, B, C, N, DM, blockIdx.y * 128, n0, smg);
}

__global__ __launch_bounds__(256, 2) void out_gemm(
    const float* __restrict__ A, const float* __restrict__ Wo, float* __restrict__ C)
{
    extern __shared__ float smg[];
    gemm_core(A, Wo, C, DM, NH * HD, blockIdx.y * 128, blockIdx.x * 128, smg);
}

// ---------------- RoPE + transpose (K/V only; Q fused into attention) ----------------
__global__ void rope_kernel(const float* __restrict__ cosT, const float* __restrict__ sinT)
{
    const int qi   = blockIdx.x;
    const int slot = blockIdx.y;
    const int d    = threadIdx.x;
    const int pos  = PAST + qi;

    if (slot < NKV) {
        const int h = slot;
        const float c = cosT[pos * HD + d];
        const float s = sinT[pos * HD + d];
        const float* src = g_kbuf + (size_t)qi * (NKV * HD) + h * HD;
        float x = src[d], y = src[d ^ 64];
        g_kt[((size_t)h * B_Q + qi) * HD + d] = x * c + ((d < 64) ? -y : y) * s;
    } else {
        const int h = slot - NKV;
        g_vt[((size_t)h * B_Q + qi) * HD + d] =
            g_vbuf[(size_t)qi * (NKV * HD) + h * HD + d];
    }
}

// ---------------- Flash attention, tf32 mma, pipelined + full ldmatrix ----------------
// 256 threads = 8 warps. Q-tile 128 (warp w owns rows w*16..+15), K-tile 64.
// Q: RoPE + scale*log2e folded at staging, register A-frags. exp2-domain softmax
// (R9-verified form). LPT grid: blockIdx.x = head, qtile = 7 - blockIdx.y so the
// heaviest CTAs (largest causal extent) launch in wave 1.
__global__ __launch_bounds__(256) void attn_tc(
    const float* __restrict__ pk, const float* __restrict__ pv,
    const float* __restrict__ cosT, const float* __restrict__ sinT)
{
    extern __shared__ float sm[];
    float* KsBuf[2] = { sm,                sm + 64 * 132 };
    float* VtBuf[2] = { sm + 2 * 64 * 132, sm + 2 * 64 * 132 + 128 * 68 };
    float (*Ps)[68] = (float(*)[68])(sm + 2 * 64 * 132 + 2 * 128 * 68);  // 128 x 68

    const int tid = threadIdx.x;
    const int w = tid >> 5, lane = tid & 31;
    const int g = lane >> 2, cq = lane & 3;
    const int h  = blockIdx.x;                     // LPT: head fastest
    const int q0 = (7 - blockIdx.y) * 128;         // heaviest qtile first
    const int kvh = h >> 2;
    const int rbase = w * 16;

    // ---- stage Q with fused RoPE + scale fold (stride 132), ldmatrix -> regs ----
#pragma unroll
    for (int p = 0; p < 16; p++) {
        int e = p * 256 + tid;
        int row = e >> 5, d4 = (e & 31) * 4;
        const float* src = &g_qbuf[(size_t)(q0 + row) * (NH * HD) + h * HD];
        float4 x = *(const float4*)&src[d4];
        float4 y = *(const float4*)&src[d4 ^ 64];
        const int pos = PAST + q0 + row;
        float4 c = *(const float4*)&cosT[pos * HD + d4];
        float4 s = *(const float4*)&sinT[pos * HD + d4];
        float sgn = (d4 < 64) ? -1.f : 1.f;
        float4 r;
        r.x = (x.x * c.x + sgn * y.x * s.x) * QSCALE;
        r.y = (x.y * c.y + sgn * y.y * s.y) * QSCALE;
        r.z = (x.z * c.z + sgn * y.z * s.z) * QSCALE;
        r.w = (x.w * c.w + sgn * y.w * s.w) * QSCALE;
        *(float4*)&sm[row * 132 + d4] =
            make_float4(f2tff(r.x), f2tff(r.y), f2tff(r.z), f2tff(r.w));
    }
    __syncthreads();

    const int lrow = rbase + ((lane >> 3) & 1) * 8 + (lane & 7);
    const int lcol = (lane >> 4) * 4;
    const uint32_t qmat = smem_u32(sm) + (lrow * 132 + lcol) * 4;
    unsigned qf[16][4];
#pragma unroll
    for (int ks = 0; ks < 16; ks++)
        ldm_x4(qf[ks], qmat + ks * 32);
    __syncthreads();   // Q staging reads done before K0/V0 STS

    const uint32_t pmat = smem_u32(&Ps[0][0]) + (lrow * 68 + lcol) * 4;

    const int g3 = lane >> 3, l7 = lane & 7;
    uint32_t kmat[2][4], vmat[2][8];
#pragma unroll
    for (int b = 0; b < 2; b++) {
        const uint32_t kb = smem_u32(KsBuf[b]);
        const uint32_t vb = smem_u32(VtBuf[b]);
#pragma unroll
        for (int ntp = 0; ntp < 4; ntp++) {
            int row = ntp * 16 + (g3 >> 1) * 8 + l7;
            kmat[b][ntp] = kb + (row * 132 + (g3 & 1) * 4) * 4;
        }
#pragma unroll
        for (int ntp = 0; ntp < 8; ntp++) {
            int row = ntp * 16 + (g3 >> 1) * 8 + l7;
            vmat[b][ntp] = vb + (row * 68 + (g3 & 1) * 4) * 4;
        }
    }

    float m_i[2], l_i[2];
    float o[16][4];
    m_i[0] = m_i[1] = -1e30f;
    l_i[0] = l_i[1] = 0.f;
#pragma unroll
    for (int nt = 0; nt < 16; nt++)
#pragma unroll
        for (int r = 0; r < 4; r++) o[nt][r] = 0.f;

    const int ntiles = ((3072 + q0 + 127) >> 6) + 1;
    const int d4c = (lane * 4) & 127;
    const int vd  = tid & 127;
    const int vk0 = (tid >> 7) * 32;

    float4 rk[8];
    float  rv[32];
#define LOAD_K(KT) do { \
        const int _jb = (KT) * 64; \
        _Pragma("unroll") \
        for (int p = 0; p < 8; p++) { \
            int j = _jb + p * 8 + w; \
            int kp = (j < SINKS_N) ? j : j + 1024; \
            rk[p] = (kp < PAST) \
                ? *(const float4*)&pk[((size_t)kvh * PAST + kp) * HD + d4c] \
                : *(const float4*)&g_kt[((size_t)kvh * B_Q + (kp - PAST)) * HD + d4c]; \
        } \
    } while (0)
#define LOAD_V(KT) do { \
        const int _jb = (KT) * 64 + vk0; \
        _Pragma("unroll") \
        for (int j = 0; j < 32; j++) { \
            int jj = _jb + j; \
            int kp = (jj < SINKS_N) ? jj : jj + 1024; \
            rv[j] = (kp < PAST) \
                ? pv[((size_t)kvh * PAST + kp) * HD + vd] \
                : g_vt[((size_t)kvh * B_Q + (kp - PAST)) * HD + vd]; \
        } \
    } while (0)
#define STS_K(BUF) do { \
        float* _d = KsBuf[BUF]; \
        _Pragma("unroll") \
        for (int p = 0; p < 8; p++) \
            *(float4*)&_d[(p * 8 + w) * 132 + d4c] = \
                make_float4(f2tff(rk[p].x), f2tff(rk[p].y), f2tff(rk[p].z), f2tff(rk[p].w)); \
    } while (0)
#define STS_V(BUF) do { \
        float* _d = VtBuf[BUF]; \
        _Pragma("unroll") \
        for (int p = 0; p < 8; p++) \
            *(float4*)&_d[vd * 68 + vk0 + p * 4] = \
                make_float4(f2tff(rv[p * 4]), f2tff(rv[p * 4 + 1]), \
                            f2tff(rv[p * 4 + 2]), f2tff(rv[p * 4 + 3])); \
    } while (0)

    // prologue: tile 0 into buffer 0
    LOAD_K(0); LOAD_V(0);
    STS_K(0);  STS_V(0);

    for (int kt = 0; kt < ntiles; kt++) {
        const int jbase = kt * 64;
        const int buf = kt & 1;
        const bool pf = (kt + 1 < ntiles);
        __syncthreads();   // buffer `buf` ready; prior readers of buf^1 done

        if (pf) LOAD_K(kt + 1);   // LDG issues early; consumed after softmax

        // ---- S = Q @ K^T : 16 rows x 64 keys per warp (exp2-scaled domain) ----
        float s[8][4];
#pragma unroll
        for (int nt = 0; nt < 8; nt++)
#pragma unroll
            for (int r = 0; r < 4; r++) s[nt][r] = 0.f;

#pragma unroll
        for (int ks = 0; ks < 16; ks++) {
#pragma unroll
            for (int ntp = 0; ntp < 4; ntp++) {
                unsigned bf[4];
                ldm_x4(bf, kmat[buf][ntp] + ks * 32);
                mma_tf32(s[2 * ntp],     qf[ks][0], qf[ks][1], qf[ks][2], qf[ks][3], bf[0], bf[1]);
                mma_tf32(s[2 * ntp + 1], qf[ks][0], qf[ks][1], qf[ks][2], qf[ks][3], bf[2], bf[3]);
            }
        }

        // ---- online softmax (base-2 domain, R9-verified) ----
#pragma unroll
        for (int half = 0; half < 2; half++) {
            const int rl  = rbase + g + half * 8;
            const int lim = 3072 + q0 + rl;
            float mx = -1e30f;
#pragma unroll
            for (int nt = 0; nt < 8; nt++)
#pragma unroll
                for (int rr = 0; rr < 2; rr++) {
                    int jg = jbase + nt * 8 + 2 * cq + rr;
                    float v = (jg <= lim) ? s[nt][half * 2 + rr] : -1e30f;
                    s[nt][half * 2 + rr] = v;
                    mx = fmaxf(mx, v);
                }
            mx = fmaxf(mx, __shfl_xor_sync(0xffffffffu, mx, 1));
            mx = fmaxf(mx, __shfl_xor_sync(0xffffffffu, mx, 2));
            float mnew = fmaxf(m_i[half], mx);
            float corr = exp2f(m_i[half] - mnew);
            m_i[half] = mnew;
            float rs = 0.f;
#pragma unroll
            for (int nt = 0; nt < 8; nt++) {
                float p0 = exp2f(s[nt][half * 2]     - mnew);
                float p1 = exp2f(s[nt][half * 2 + 1] - mnew);
                rs += p0 + p1;
                *(float2*)&Ps[rl][nt * 8 + 2 * cq] = make_float2(f2tff(p0), f2tff(p1));
            }
            rs += __shfl_xor_sync(0xffffffffu, rs, 1);
            rs += __shfl_xor_sync(0xffffffffu, rs, 2);
            l_i[half] = l_i[half] * corr + rs;
#pragma unroll
            for (int nt = 0; nt < 16; nt++) {
                o[nt][half * 2]     *= corr;
                o[nt][half * 2 + 1] *= corr;
            }
        }
        __syncwarp();   // Ps is warp-private

        if (pf) { STS_K(buf ^ 1); LOAD_V(kt + 1); }

        // ---- O += P @ V : 16 rows x 128 d per warp, k-dim 64 ----
#pragma unroll
        for (int ks = 0; ks < 8; ks++) {
            unsigned a[4];
            ldm_x4(a, pmat + ks * 32);
#pragma unroll
            for (int ntp = 0; ntp < 8; ntp++) {
                unsigned bf[4];
                ldm_x4(bf, vmat[buf][ntp] + ks * 32);
                mma_tf32(o[2 * ntp],     a[0], a[1], a[2], a[3], bf[0], bf[1]);
                mma_tf32(o[2 * ntp + 1], a[0], a[1], a[2], a[3], bf[2], bf[3]);
            }
        }

        if (pf) STS_V(buf ^ 1);
    }

    // ---- epilogue ----
    float inv0 = 1.0f / l_i[0];
    float inv1 = 1.0f / l_i[1];
    int row0 = q0 + rbase + g;
#pragma unroll
    for (int nt = 0; nt < 16; nt++) {
        int dd = nt * 8 + 2 * cq;
        *(float2*)&g_attn[(size_t)row0 * (NH * HD) + h * HD + dd] =
            make_float2(o[nt][0] * inv0, o[nt][1] * inv0);
        *(float2*)&g_attn[(size_t)(row0 + 8) * (NH * HD) + h * HD + dd] =
            make_float2(o[nt][2] * inv1, o[nt][3] * inv1);
    }
}

// ---------------- launch ----------------
extern "C" void kernel_launch(void* const* d_in, const int* in_sizes, int n_in,
                              void* d_out, int out_size)
{
    (void)in_sizes; (void)n_in; (void)out_size;
    const float* hidden = (const float*)d_in[0];
    const float* Wq     = (const float*)d_in[1];
    const float* Wk     = (const float*)d_in[2];
    const float* Wv     = (const float*)d_in[3];
    const float* Wo     = (const float*)d_in[4];
    const float* past_k = (const float*)d_in[5];
    const float* past_v = (const float*)d_in[6];
    const float* cosT   = (const float*)d_in[7];
    const float* sinT   = (const float*)d_in[8];

    void *p_attn;
    cudaGetSymbolAddress(&p_attn, g_attn);

    const int gemm_smem = (2 * 128 * 36 + 2 * 32 * 132) * 4;            // 70656 B
    cudaFuncSetAttribute(qkv_gemm, cudaFuncAttributeMaxDynamicSharedMemorySize, gemm_smem);
    cudaFuncSetAttribute(out_gemm, cudaFuncAttributeMaxDynamicSharedMemorySize, gemm_smem);
    const int attn_smem = (2 * 64 * 132 + 2 * 128 * 68 + 128 * 68) * 4; // 172032 B
    cudaFuncSetAttribute(attn_tc, cudaFuncAttributeMaxDynamicSharedMemorySize, attn_smem);

    dim3 blk(256);
    qkv_gemm<<<dim3(48, 8), blk, gemm_smem>>>(hidden, Wq, Wk, Wv);
    rope_kernel<<<dim3(B_Q, 2 * NKV), 128>>>(cosT, sinT);
    attn_tc<<<dim3(NH, B_Q / 128), blk, attn_smem>>>(past_k, past_v, cosT, sinT);
    out_gemm<<<dim3(32, 8), blk, gemm_smem>>>((const float*)p_attn, Wo, (float*)d_out);
}